// round 9
// baseline (speedup 1.0000x reference)
#include <cuda_runtime.h>
#include <math.h>

static constexpr int NIN   = 8192;
static constexpr int N_HID = 8192;
static constexpr int N_OUT = 1024;
static constexpr int SB    = 32;                          // x-stats blocks (tail)
static constexpr int ROW_BLOCKS   = N_HID + N_OUT;        // 9216
static constexpr int TOTAL_BLOCKS = ROW_BLOCKS + SB;      // 9248

// ---------------- scratch (no allocations allowed) ----------------
__device__ float g_z[NIN];
__device__ float g_hidden[N_HID];
__device__ float g_w1sum[N_HID];
__device__ float g_w2sum[N_OUT];

// x-stats partials (written by big_kernel tail blocks)
__device__ float              g_psum[SB];
__device__ unsigned int       g_pmin[SB];
__device__ unsigned long long g_pmax[SB];

__device__ __forceinline__ unsigned int fkey(float v) {
    unsigned u = __float_as_uint(v);
    return (u & 0x80000000u) ? ~u : (u | 0x80000000u);
}
__device__ __forceinline__ float fdec(unsigned int k) {
    unsigned u = (k & 0x80000000u) ? (k ^ 0x80000000u) : ~k;
    return __uint_as_float(u);
}

// ---------------------------------------------------------------------------
// big_kernel — IDENTICAL to R7/R8 (measured 45.4us, 6.72 TB/s). Do not touch.
//   bids [0, 9216)   : W row sums (pure stream)
//   bids [9216, 9248): z = exp(x) + x-stats partials (free tail wave)
// ---------------------------------------------------------------------------
__global__ void __launch_bounds__(256) big_kernel(const float* __restrict__ x,
                                                  const float* __restrict__ W1,
                                                  const float* __restrict__ W2)
{
    const int bid = blockIdx.x;
    const int tid = threadIdx.x;

    if (bid >= ROW_BLOCKS) {
        const int sb = bid - ROW_BLOCKS;
        const int j  = sb * 256 + tid;
        const float v = expf(x[j]);
        g_z[j] = v;

        __shared__ float              ss[256];
        __shared__ unsigned int       smn[256];
        __shared__ unsigned long long smx[256];
        ss[tid]  = v;
        const unsigned k = fkey(v);
        smn[tid] = k;
        smx[tid] = ((unsigned long long)k << 32) | (unsigned)j;
        __syncthreads();
        for (int o = 128; o > 0; o >>= 1) {
            if (tid < o) {
                ss[tid]  += ss[tid + o];
                smn[tid]  = min(smn[tid], smn[tid + o]);
                smx[tid]  = max(smx[tid], smx[tid + o]);
            }
            __syncthreads();
        }
        if (tid == 0) {
            g_psum[sb] = ss[0];
            g_pmin[sb] = smn[0];
            g_pmax[sb] = smx[0];
        }
        return;
    }

    const bool isW2 = (bid >= N_HID);
    const float* __restrict__ W = isW2 ? W2 : W1;
    const int  row  = isW2 ? (bid - N_HID) : bid;
    const float4* __restrict__ Wr =
        reinterpret_cast<const float4*>(W + (size_t)row * NIN);

    float acc = 0.f;
    #pragma unroll
    for (int i = 0; i < NIN / 4 / 256; ++i) {
        float4 v = __ldcs(Wr + tid + i * 256);
        acc += (v.x + v.y) + (v.z + v.w);
    }
    #pragma unroll
    for (int o = 16; o > 0; o >>= 1) acc += __shfl_down_sync(0xffffffffu, acc, o);

    __shared__ float swp[8];
    const int wid = tid >> 5, lane = tid & 31;
    if (lane == 0) swp[wid] = acc;
    __syncthreads();

    if (tid == 0) {
        float Wsum = 0.f;
        #pragma unroll
        for (int w = 0; w < 8; ++w) Wsum += swp[w];
        if (isW2) g_w2sum[row] = Wsum; else g_w1sum[row] = Wsum;
    }
}

// ---------------------------------------------------------------------------
// finale — ONE block x 1024 threads, everything after the stream:
//   phase 0: warp 0 combines the 32 x-stats partials (shuffle tree, fixed order)
//   phase 1: layer-1 closed form for all 8192 rows (8 rows/thread, 8-deep MLP
//            scattered W1 loads), results -> g_hidden + in-register partials
//   phase 2: 1024-wide fixed-order tree -> hidden stats
//   phase 3: layer-2 closed form, one output row per thread -> out
// ---------------------------------------------------------------------------
__global__ void __launch_bounds__(1024) finale_kernel(const float* __restrict__ W1,
                                                      const float* __restrict__ W2,
                                                      float* __restrict__ out)
{
    const int tid = threadIdx.x;
    __shared__ float s_Zsum, s_zmin, s_zmax;
    __shared__ int   s_jlast;

    // ---- phase 0: combine x-stats partials ----
    if (tid < 32) {
        float sum = g_psum[tid];
        unsigned mnk = g_pmin[tid];
        unsigned long long mx = g_pmax[tid];
        #pragma unroll
        for (int o = 16; o > 0; o >>= 1) {
            sum += __shfl_down_sync(0xffffffffu, sum, o);
            mnk  = min(mnk, __shfl_down_sync(0xffffffffu, mnk, o));
            mx   = max(mx,  __shfl_down_sync(0xffffffffu, mx,  o));
        }
        if (tid == 0) {
            s_Zsum  = sum;
            s_zmin  = fdec(mnk);
            s_zmax  = fdec((unsigned)(mx >> 32));
            s_jlast = (int)(unsigned)mx;
        }
    }
    __syncthreads();

    const float xZsum = s_Zsum, xzmin = s_zmin, xzmax = s_zmax;
    const int   xjlast = s_jlast;

    // ---- phase 1: layer-1 closed form, 8 rows per thread ----
    float hsum = 0.f;
    unsigned hmink = 0xFFFFFFFFu;
    unsigned long long hmaxp = 0ULL;

    #pragma unroll
    for (int i = 0; i < N_HID / 1024; ++i) {
        const int r = tid + i * 1024;
        const float Wsum = g_w1sum[r];
        const float tmp = Wsum * xZsum / (Wsum - 1.f);
        float result = INFINITY;

        if (Wsum > 1.f) {
            if (xzmin <= tmp) {                    // first mismatch at i=0 -> k=n-1
                float Wc = Wsum - W1[(size_t)r * NIN + xjlast];
                float Zc = xZsum - xzmax;
                result = Wc * Zc / (Wc - 1.f);
            }                                      // else: no mismatch -> inf
        } else {
            // rare general path (never taken for this data): serial row scan
            int cnt = 0; float sle = 0.f, wle = 0.f, m = -INFINITY; int jm = -1;
            for (int j = 0; j < NIN; ++j) {
                float zj = g_z[j];
                if (zj <= tmp) {
                    cnt++; sle += zj; wle += W1[(size_t)r * NIN + j];
                    if (zj > m || (zj == m && j > jm)) { m = zj; jm = j; }
                }
            }
            if (cnt == NIN) {
            } else if (cnt == 0) {
                float Wc = Wsum - W1[(size_t)r * NIN + xjlast];
                float Zc = xZsum - xzmax;
                result = Wc * Zc / (Wc - 1.f);
            } else if (cnt - 1 != 0) {
                float Zc = sle - m;
                float Wc = wle - W1[(size_t)r * NIN + jm];
                result = Wc * Zc / (Wc - 1.f);
            }
        }
        g_hidden[r] = result;

        hsum += result;
        const unsigned hk = fkey(result);
        hmink = min(hmink, hk);
        hmaxp = max(hmaxp, ((unsigned long long)hk << 32) | (unsigned)r);
    }

    // ---- phase 2: hidden stats (1024-wide fixed-order tree) ----
    __shared__ float              hs[1024];
    __shared__ unsigned int       hn[1024];
    __shared__ unsigned long long hx[1024];
    hs[tid] = hsum; hn[tid] = hmink; hx[tid] = hmaxp;
    __syncthreads();
    for (int o = 512; o > 0; o >>= 1) {
        if (tid < o) {
            hs[tid] += hs[tid + o];
            hn[tid]  = min(hn[tid], hn[tid + o]);
            hx[tid]  = max(hx[tid], hx[tid + o]);
        }
        __syncthreads();
    }
    const float Zsum = hs[0];
    const float zmin = fdec(hn[0]);
    const float zmax = fdec((unsigned)(hx[0] >> 32));
    const int   jlast = (int)(unsigned)hx[0];
    __syncthreads();

    // ---- phase 3: layer-2 closed form, one row per thread ----
    const int r = tid;
    if (r >= N_OUT) return;

    const float Wsum = g_w2sum[r];
    const float tmp = Wsum * Zsum / (Wsum - 1.f);
    float result = INFINITY;

    if (Wsum > 1.f) {
        if (zmin <= tmp) {
            float Wc = Wsum - W2[(size_t)r * NIN + jlast];
            float Zc = Zsum - zmax;
            result = Wc * Zc / (Wc - 1.f);
        }
    } else {
        // rare general path (never taken for this data): serial row scan
        int cnt = 0; float sle = 0.f, wle = 0.f, m = -INFINITY; int jmm = -1;
        for (int j = 0; j < NIN; ++j) {
            float zj = g_hidden[j];
            if (zj <= tmp) {
                cnt++; sle += zj; wle += W2[(size_t)r * NIN + j];
                if (zj > m || (zj == m && j > jmm)) { m = zj; jmm = j; }
            }
        }
        if (cnt == NIN) {
        } else if (cnt == 0) {
            float Wc = Wsum - W2[(size_t)r * NIN + jlast];
            float Zc = Zsum - zmax;
            result = Wc * Zc / (Wc - 1.f);
        } else if (cnt - 1 != 0) {
            float Zc = sle - m;
            float Wc = wle - W2[(size_t)r * NIN + jmm];
            result = Wc * Zc / (Wc - 1.f);
        }
    }
    out[r] = result;
}

extern "C" void kernel_launch(void* const* d_in, const int* in_sizes, int n_in,
                              void* d_out, int out_size)
{
    const float* x  = (const float*)d_in[0];
    const float* W1 = (const float*)d_in[1];
    const float* W2 = (const float*)d_in[2];
    float* out = (float*)d_out;

    big_kernel<<<TOTAL_BLOCKS, 256>>>(x, W1, W2);      // stream + tail stats
    finale_kernel<<<1, 1024>>>(W1, W2, out);           // everything else
}

// round 10
// speedup vs baseline: 1.0565x; 1.0565x over previous
#include <cuda_runtime.h>
#include <math.h>

static constexpr int NIN   = 8192;
static constexpr int N_HID = 8192;
static constexpr int N_OUT = 1024;
static constexpr int SB    = 32;                     // x-stats blocks (tail)
static constexpr int W1_BLOCKS = N_HID / 2;          // 4096 (2 rows per block)
static constexpr int W2_BLOCKS = N_OUT / 2;          // 512
static constexpr int ROW_BLOCKS   = W1_BLOCKS + W2_BLOCKS;   // 4608
static constexpr int TOTAL_BLOCKS = ROW_BLOCKS + SB;         // 4640
static constexpr int FA_BLOCKS    = 32;

// ---------------- scratch (no allocations allowed) ----------------
__device__ float g_z[NIN];
__device__ float g_hidden[N_HID];
__device__ float g_w1sum[N_HID];
__device__ float g_w2sum[N_OUT];

// x-stats partials (written by big_kernel tail blocks)
__device__ float              g_psum[SB];
__device__ unsigned int       g_pmin[SB];
__device__ unsigned long long g_pmax[SB];
// hidden-stats partials (written by finaleA blocks)
__device__ float              g_qsum[FA_BLOCKS];
__device__ unsigned int       g_qmin[FA_BLOCKS];
__device__ unsigned long long g_qmax[FA_BLOCKS];

__device__ __forceinline__ unsigned int fkey(float v) {
    unsigned u = __float_as_uint(v);
    return (u & 0x80000000u) ? ~u : (u | 0x80000000u);
}
__device__ __forceinline__ float fdec(unsigned int k) {
    unsigned u = (k & 0x80000000u) ? (k ^ 0x80000000u) : ~k;
    return __uint_as_float(u);
}

// ---------------------------------------------------------------------------
// big_kernel — 2 rows per block (16 independent float4 loads/thread):
//   bids [0, 4096)     : W1 rows 2b, 2b+1
//   bids [4096, 4608)  : W2 rows 2(b-4096), +1
//   bids [4608, 4640)  : z = exp(x) + x-stats partials (tail wave)
// ---------------------------------------------------------------------------
__global__ void __launch_bounds__(256) big_kernel(const float* __restrict__ x,
                                                  const float* __restrict__ W1,
                                                  const float* __restrict__ W2)
{
    const int bid = blockIdx.x;
    const int tid = threadIdx.x;

    if (bid >= ROW_BLOCKS) {
        const int sb = bid - ROW_BLOCKS;
        const int j  = sb * 256 + tid;
        const float v = expf(x[j]);
        g_z[j] = v;

        __shared__ float              ss[256];
        __shared__ unsigned int       smn[256];
        __shared__ unsigned long long smx[256];
        ss[tid]  = v;
        const unsigned k = fkey(v);
        smn[tid] = k;
        smx[tid] = ((unsigned long long)k << 32) | (unsigned)j;
        __syncthreads();
        for (int o = 128; o > 0; o >>= 1) {
            if (tid < o) {
                ss[tid]  += ss[tid + o];
                smn[tid]  = min(smn[tid], smn[tid + o]);
                smx[tid]  = max(smx[tid], smx[tid + o]);
            }
            __syncthreads();
        }
        if (tid == 0) {
            g_psum[sb] = ss[0];
            g_pmin[sb] = smn[0];
            g_pmax[sb] = smx[0];
        }
        return;
    }

    const bool isW2 = (bid >= W1_BLOCKS);
    const float* __restrict__ W = isW2 ? W2 : W1;
    const int  row0 = (isW2 ? (bid - W1_BLOCKS) : bid) * 2;
    const float4* __restrict__ Wr0 =
        reinterpret_cast<const float4*>(W + (size_t)row0 * NIN);
    const float4* __restrict__ Wr1 = Wr0 + NIN / 4;

    float a0 = 0.f, a1 = 0.f;
    #pragma unroll
    for (int i = 0; i < NIN / 4 / 256; ++i) {
        float4 v0 = __ldcs(Wr0 + tid + i * 256);
        float4 v1 = __ldcs(Wr1 + tid + i * 256);
        a0 += (v0.x + v0.y) + (v0.z + v0.w);
        a1 += (v1.x + v1.y) + (v1.z + v1.w);
    }
    #pragma unroll
    for (int o = 16; o > 0; o >>= 1) {
        a0 += __shfl_down_sync(0xffffffffu, a0, o);
        a1 += __shfl_down_sync(0xffffffffu, a1, o);
    }

    __shared__ float swp0[8], swp1[8];
    const int wid = tid >> 5, lane = tid & 31;
    if (lane == 0) { swp0[wid] = a0; swp1[wid] = a1; }
    __syncthreads();

    if (tid == 0) {
        float s0 = 0.f, s1 = 0.f;
        #pragma unroll
        for (int w = 0; w < 8; ++w) { s0 += swp0[w]; s1 += swp1[w]; }
        if (isW2) { g_w2sum[row0] = s0; g_w2sum[row0 + 1] = s1; }
        else      { g_w1sum[row0] = s0; g_w1sum[row0 + 1] = s1; }
    }
}

// ---------------------------------------------------------------------------
// finaleA (grid 32 x 256) — IDENTICAL to R8 (proven ~2us):
//   1) warp 0 combines the 32 x-stats partials (shuffle tree, fixed order)
//   2) each thread: layer-1 closed form for one row -> g_hidden
//   3) block-reduce the 256 fresh results -> hidden-stats partial
// ---------------------------------------------------------------------------
__global__ void __launch_bounds__(256) finaleA_kernel(const float* __restrict__ W1)
{
    const int tid = threadIdx.x;
    __shared__ float s_Zsum, s_zmin, s_zmax;
    __shared__ int   s_jlast;

    if (tid < 32) {
        float sum = g_psum[tid];
        unsigned mnk = g_pmin[tid];
        unsigned long long mx = g_pmax[tid];
        #pragma unroll
        for (int o = 16; o > 0; o >>= 1) {
            sum += __shfl_down_sync(0xffffffffu, sum, o);
            mnk  = min(mnk, __shfl_down_sync(0xffffffffu, mnk, o));
            mx   = max(mx,  __shfl_down_sync(0xffffffffu, mx,  o));
        }
        if (tid == 0) {
            s_Zsum  = sum;
            s_zmin  = fdec(mnk);
            s_zmax  = fdec((unsigned)(mx >> 32));
            s_jlast = (int)(unsigned)mx;
        }
    }
    __syncthreads();

    const float Zsum = s_Zsum, zmin = s_zmin, zmax = s_zmax;
    const int   jlast = s_jlast;
    const int   r = blockIdx.x * 256 + tid;
    const float Wsum = g_w1sum[r];
    const float tmp = Wsum * Zsum / (Wsum - 1.f);
    float result = INFINITY;

    if (Wsum > 1.f) {
        if (zmin <= tmp) {                        // first mismatch at i=0 -> k=n-1
            float Wc = Wsum - W1[(size_t)r * NIN + jlast];
            float Zc = Zsum - zmax;
            result = Wc * Zc / (Wc - 1.f);
        }                                         // else: no mismatch -> inf
    } else {
        // rare general path (never taken for this data): serial row scan
        int cnt = 0; float sle = 0.f, wle = 0.f, m = -INFINITY; int jm = -1;
        for (int j = 0; j < NIN; ++j) {
            float zj = g_z[j];
            if (zj <= tmp) {
                cnt++; sle += zj; wle += W1[(size_t)r * NIN + j];
                if (zj > m || (zj == m && j > jm)) { m = zj; jm = j; }
            }
        }
        if (cnt == NIN) {
        } else if (cnt == 0) {
            float Wc = Wsum - W1[(size_t)r * NIN + jlast];
            float Zc = Zsum - zmax;
            result = Wc * Zc / (Wc - 1.f);
        } else if (cnt - 1 != 0) {
            float Zc = sle - m;
            float Wc = wle - W1[(size_t)r * NIN + jm];
            result = Wc * Zc / (Wc - 1.f);
        }
    }
    g_hidden[r] = result;

    // ---- reduce this block's 256 results to a hidden-stats partial ----
    __shared__ float              hs[256];
    __shared__ unsigned int       hn[256];
    __shared__ unsigned long long hx[256];
    hs[tid] = result;
    const unsigned hk = fkey(result);
    hn[tid] = hk;
    hx[tid] = ((unsigned long long)hk << 32) | (unsigned)r;
    __syncthreads();
    for (int o = 128; o > 0; o >>= 1) {
        if (tid < o) {
            hs[tid] += hs[tid + o];
            hn[tid]  = min(hn[tid], hn[tid + o]);
            hx[tid]  = max(hx[tid], hx[tid + o]);
        }
        __syncthreads();
    }
    if (tid == 0) {
        g_qsum[blockIdx.x] = hs[0];
        g_qmin[blockIdx.x] = hn[0];
        g_qmax[blockIdx.x] = hx[0];
    }
}

// ---------------------------------------------------------------------------
// finaleB (1 block x 256) — IDENTICAL to R8: combine 32 hidden partials
// (one warp, fixed order), then layer-2 closed form (4 rows/thread).
// ---------------------------------------------------------------------------
__global__ void __launch_bounds__(256) finaleB_kernel(const float* __restrict__ W2,
                                                      float* __restrict__ out)
{
    const int tid = threadIdx.x;
    __shared__ float s_Zsum, s_zmin, s_zmax;
    __shared__ int   s_jlast;

    if (tid < 32) {
        float sum = g_qsum[tid];
        unsigned mnk = g_qmin[tid];
        unsigned long long mx = g_qmax[tid];
        #pragma unroll
        for (int o = 16; o > 0; o >>= 1) {
            sum += __shfl_down_sync(0xffffffffu, sum, o);
            mnk  = min(mnk, __shfl_down_sync(0xffffffffu, mnk, o));
            mx   = max(mx,  __shfl_down_sync(0xffffffffu, mx,  o));
        }
        if (tid == 0) {
            s_Zsum  = sum;
            s_zmin  = fdec(mnk);
            s_zmax  = fdec((unsigned)(mx >> 32));
            s_jlast = (int)(unsigned)mx;
        }
    }
    __syncthreads();

    const float Zsum = s_Zsum, zmin = s_zmin, zmax = s_zmax;
    const int   jlast = s_jlast;

    #pragma unroll
    for (int r = tid; r < N_OUT; r += 256) {
        const float Wsum = g_w2sum[r];
        const float tmp = Wsum * Zsum / (Wsum - 1.f);
        float result = INFINITY;

        if (Wsum > 1.f) {
            if (zmin <= tmp) {
                float Wc = Wsum - W2[(size_t)r * NIN + jlast];
                float Zc = Zsum - zmax;
                result = Wc * Zc / (Wc - 1.f);
            }
        } else {
            // rare general path (never taken for this data): serial row scan
            int cnt = 0; float sle = 0.f, wle = 0.f, m = -INFINITY; int jmm = -1;
            for (int j = 0; j < NIN; ++j) {
                float zj = g_hidden[j];
                if (zj <= tmp) {
                    cnt++; sle += zj; wle += W2[(size_t)r * NIN + j];
                    if (zj > m || (zj == m && j > jmm)) { m = zj; jmm = j; }
                }
            }
            if (cnt == NIN) {
            } else if (cnt == 0) {
                float Wc = Wsum - W2[(size_t)r * NIN + jlast];
                float Zc = Zsum - zmax;
                result = Wc * Zc / (Wc - 1.f);
            } else if (cnt - 1 != 0) {
                float Zc = sle - m;
                float Wc = wle - W2[(size_t)r * NIN + jmm];
                result = Wc * Zc / (Wc - 1.f);
            }
        }
        out[r] = result;
    }
}

extern "C" void kernel_launch(void* const* d_in, const int* in_sizes, int n_in,
                              void* d_out, int out_size)
{
    const float* x  = (const float*)d_in[0];
    const float* W1 = (const float*)d_in[1];
    const float* W2 = (const float*)d_in[2];
    float* out = (float*)d_out;

    big_kernel<<<TOTAL_BLOCKS, 256>>>(x, W1, W2);     // stream (2 rows/block) + tail stats
    finaleA_kernel<<<FA_BLOCKS, 256>>>(W1);           // layer-1 + hidden partials
    finaleB_kernel<<<1, 256>>>(W2, out);              // combine + layer-2
}

// round 11
// speedup vs baseline: 1.0966x; 1.0379x over previous
#include <cuda_runtime.h>
#include <math.h>

static constexpr int NIN   = 8192;
static constexpr int N_HID = 8192;
static constexpr int N_OUT = 1024;
static constexpr int SB    = 32;                          // x-stats blocks (tail)
static constexpr int ROW_BLOCKS   = N_HID + N_OUT;        // 9216
static constexpr int TOTAL_BLOCKS = ROW_BLOCKS + SB;      // 9248
static constexpr int FA_BLOCKS    = 32;

// ---------------- scratch (no allocations allowed) ----------------
__device__ float g_z[NIN];
__device__ float g_hidden[N_HID];
__device__ float g_w1sum[N_HID];
__device__ float g_w2sum[N_OUT];

// x-stats partials (written by big_kernel tail blocks)
__device__ float              g_psum[SB];
__device__ unsigned int       g_pmin[SB];
__device__ unsigned long long g_pmax[SB];
// hidden-stats partials (written by finaleA blocks)
__device__ float              g_qsum[FA_BLOCKS];
__device__ unsigned int       g_qmin[FA_BLOCKS];
__device__ unsigned long long g_qmax[FA_BLOCKS];

__device__ __forceinline__ unsigned int fkey(float v) {
    unsigned u = __float_as_uint(v);
    return (u & 0x80000000u) ? ~u : (u | 0x80000000u);
}
__device__ __forceinline__ float fdec(unsigned int k) {
    unsigned u = (k & 0x80000000u) ? (k ^ 0x80000000u) : ~k;
    return __uint_as_float(u);
}

// PDL device-side primitives (sm_90+)
__device__ __forceinline__ void pdl_trigger() {
    asm volatile("griddepcontrol.launch_dependents;" ::: "memory");
}
__device__ __forceinline__ void pdl_wait() {
    asm volatile("griddepcontrol.wait;" ::: "memory");
}

// ---------------------------------------------------------------------------
// big_kernel — IDENTICAL to R8 (measured 45.4us, 6.72 TB/s) + early PDL trigger.
//   bids [0, 9216)   : W row sums (pure stream)
//   bids [9216, 9248): z = exp(x) + x-stats partials (free tail wave)
// ---------------------------------------------------------------------------
__global__ void __launch_bounds__(256) big_kernel(const float* __restrict__ x,
                                                  const float* __restrict__ W1,
                                                  const float* __restrict__ W2)
{
    pdl_trigger();   // let finaleA pre-launch during our last wave

    const int bid = blockIdx.x;
    const int tid = threadIdx.x;

    if (bid >= ROW_BLOCKS) {
        const int sb = bid - ROW_BLOCKS;
        const int j  = sb * 256 + tid;
        const float v = expf(x[j]);
        g_z[j] = v;

        __shared__ float              ss[256];
        __shared__ unsigned int       smn[256];
        __shared__ unsigned long long smx[256];
        ss[tid]  = v;
        const unsigned k = fkey(v);
        smn[tid] = k;
        smx[tid] = ((unsigned long long)k << 32) | (unsigned)j;
        __syncthreads();
        for (int o = 128; o > 0; o >>= 1) {
            if (tid < o) {
                ss[tid]  += ss[tid + o];
                smn[tid]  = min(smn[tid], smn[tid + o]);
                smx[tid]  = max(smx[tid], smx[tid + o]);
            }
            __syncthreads();
        }
        if (tid == 0) {
            g_psum[sb] = ss[0];
            g_pmin[sb] = smn[0];
            g_pmax[sb] = smx[0];
        }
        return;
    }

    const bool isW2 = (bid >= N_HID);
    const float* __restrict__ W = isW2 ? W2 : W1;
    const int  row  = isW2 ? (bid - N_HID) : bid;
    const float4* __restrict__ Wr =
        reinterpret_cast<const float4*>(W + (size_t)row * NIN);

    float acc = 0.f;
    #pragma unroll
    for (int i = 0; i < NIN / 4 / 256; ++i) {
        float4 v = __ldcs(Wr + tid + i * 256);
        acc += (v.x + v.y) + (v.z + v.w);
    }
    #pragma unroll
    for (int o = 16; o > 0; o >>= 1) acc += __shfl_down_sync(0xffffffffu, acc, o);

    __shared__ float swp[8];
    const int wid = tid >> 5, lane = tid & 31;
    if (lane == 0) swp[wid] = acc;
    __syncthreads();

    if (tid == 0) {
        float Wsum = 0.f;
        #pragma unroll
        for (int w = 0; w < 8; ++w) Wsum += swp[w];
        if (isW2) g_w2sum[row] = Wsum; else g_w1sum[row] = Wsum;
    }
}

// ---------------------------------------------------------------------------
// finaleA (grid 32 x 256) — IDENTICAL to R8 + PDL wait/trigger:
//   1) warp 0 combines the 32 x-stats partials (shuffle tree, fixed order)
//   2) each thread: layer-1 closed form for one row -> g_hidden
//   3) block-reduce the 256 fresh results -> hidden-stats partial
// ---------------------------------------------------------------------------
__global__ void __launch_bounds__(256) finaleA_kernel(const float* __restrict__ W1)
{
    pdl_trigger();   // let finaleB pre-launch
    pdl_wait();      // big_kernel's writes fully visible after this

    const int tid = threadIdx.x;
    __shared__ float s_Zsum, s_zmin, s_zmax;
    __shared__ int   s_jlast;

    if (tid < 32) {
        float sum = g_psum[tid];
        unsigned mnk = g_pmin[tid];
        unsigned long long mx = g_pmax[tid];
        #pragma unroll
        for (int o = 16; o > 0; o >>= 1) {
            sum += __shfl_down_sync(0xffffffffu, sum, o);
            mnk  = min(mnk, __shfl_down_sync(0xffffffffu, mnk, o));
            mx   = max(mx,  __shfl_down_sync(0xffffffffu, mx,  o));
        }
        if (tid == 0) {
            s_Zsum  = sum;
            s_zmin  = fdec(mnk);
            s_zmax  = fdec((unsigned)(mx >> 32));
            s_jlast = (int)(unsigned)mx;
        }
    }
    __syncthreads();

    const float Zsum = s_Zsum, zmin = s_zmin, zmax = s_zmax;
    const int   jlast = s_jlast;
    const int   r = blockIdx.x * 256 + tid;
    const float Wsum = g_w1sum[r];
    const float tmp = Wsum * Zsum / (Wsum - 1.f);
    float result = INFINITY;

    if (Wsum > 1.f) {
        if (zmin <= tmp) {                        // first mismatch at i=0 -> k=n-1
            float Wc = Wsum - W1[(size_t)r * NIN + jlast];
            float Zc = Zsum - zmax;
            result = Wc * Zc / (Wc - 1.f);
        }                                         // else: no mismatch -> inf
    } else {
        // rare general path (never taken for this data): serial row scan
        int cnt = 0; float sle = 0.f, wle = 0.f, m = -INFINITY; int jm = -1;
        for (int j = 0; j < NIN; ++j) {
            float zj = g_z[j];
            if (zj <= tmp) {
                cnt++; sle += zj; wle += W1[(size_t)r * NIN + j];
                if (zj > m || (zj == m && j > jm)) { m = zj; jm = j; }
            }
        }
        if (cnt == NIN) {
        } else if (cnt == 0) {
            float Wc = Wsum - W1[(size_t)r * NIN + jlast];
            float Zc = Zsum - zmax;
            result = Wc * Zc / (Wc - 1.f);
        } else if (cnt - 1 != 0) {
            float Zc = sle - m;
            float Wc = wle - W1[(size_t)r * NIN + jm];
            result = Wc * Zc / (Wc - 1.f);
        }
    }
    g_hidden[r] = result;

    // ---- reduce this block's 256 results to a hidden-stats partial ----
    __shared__ float              hs[256];
    __shared__ unsigned int       hn[256];
    __shared__ unsigned long long hx[256];
    hs[tid] = result;
    const unsigned hk = fkey(result);
    hn[tid] = hk;
    hx[tid] = ((unsigned long long)hk << 32) | (unsigned)r;
    __syncthreads();
    for (int o = 128; o > 0; o >>= 1) {
        if (tid < o) {
            hs[tid] += hs[tid + o];
            hn[tid]  = min(hn[tid], hn[tid + o]);
            hx[tid]  = max(hx[tid], hx[tid + o]);
        }
        __syncthreads();
    }
    if (tid == 0) {
        g_qsum[blockIdx.x] = hs[0];
        g_qmin[blockIdx.x] = hn[0];
        g_qmax[blockIdx.x] = hx[0];
    }
}

// ---------------------------------------------------------------------------
// finaleB (1 block x 256) — IDENTICAL to R8 + PDL wait: combine 32 hidden
// partials (one warp, fixed order), then layer-2 closed form (4 rows/thread).
// ---------------------------------------------------------------------------
__global__ void __launch_bounds__(256) finaleB_kernel(const float* __restrict__ W2,
                                                      float* __restrict__ out)
{
    pdl_wait();      // finaleA's writes fully visible after this

    const int tid = threadIdx.x;
    __shared__ float s_Zsum, s_zmin, s_zmax;
    __shared__ int   s_jlast;

    if (tid < 32) {
        float sum = g_qsum[tid];
        unsigned mnk = g_qmin[tid];
        unsigned long long mx = g_qmax[tid];
        #pragma unroll
        for (int o = 16; o > 0; o >>= 1) {
            sum += __shfl_down_sync(0xffffffffu, sum, o);
            mnk  = min(mnk, __shfl_down_sync(0xffffffffu, mnk, o));
            mx   = max(mx,  __shfl_down_sync(0xffffffffu, mx,  o));
        }
        if (tid == 0) {
            s_Zsum  = sum;
            s_zmin  = fdec(mnk);
            s_zmax  = fdec((unsigned)(mx >> 32));
            s_jlast = (int)(unsigned)mx;
        }
    }
    __syncthreads();

    const float Zsum = s_Zsum, zmin = s_zmin, zmax = s_zmax;
    const int   jlast = s_jlast;

    #pragma unroll
    for (int r = tid; r < N_OUT; r += 256) {
        const float Wsum = g_w2sum[r];
        const float tmp = Wsum * Zsum / (Wsum - 1.f);
        float result = INFINITY;

        if (Wsum > 1.f) {
            if (zmin <= tmp) {
                float Wc = Wsum - W2[(size_t)r * NIN + jlast];
                float Zc = Zsum - zmax;
                result = Wc * Zc / (Wc - 1.f);
            }
        } else {
            // rare general path (never taken for this data): serial row scan
            int cnt = 0; float sle = 0.f, wle = 0.f, m = -INFINITY; int jmm = -1;
            for (int j = 0; j < NIN; ++j) {
                float zj = g_hidden[j];
                if (zj <= tmp) {
                    cnt++; sle += zj; wle += W2[(size_t)r * NIN + j];
                    if (zj > m || (zj == m && j > jmm)) { m = zj; jmm = j; }
                }
            }
            if (cnt == NIN) {
            } else if (cnt == 0) {
                float Wc = Wsum - W2[(size_t)r * NIN + jlast];
                float Zc = Zsum - zmax;
                result = Wc * Zc / (Wc - 1.f);
            } else if (cnt - 1 != 0) {
                float Zc = sle - m;
                float Wc = wle - W2[(size_t)r * NIN + jmm];
                result = Wc * Zc / (Wc - 1.f);
            }
        }
        out[r] = result;
    }
}

extern "C" void kernel_launch(void* const* d_in, const int* in_sizes, int n_in,
                              void* d_out, int out_size)
{
    const float* x  = (const float*)d_in[0];
    const float* W1 = (const float*)d_in[1];
    const float* W2 = (const float*)d_in[2];
    float* out = (float*)d_out;

    // 1) stream + tail stats (plain launch)
    big_kernel<<<TOTAL_BLOCKS, 256>>>(x, W1, W2);

    // 2) finaleA with PDL: pre-launches during big_kernel's last wave
    {
        cudaLaunchAttribute attr[1];
        attr[0].id = cudaLaunchAttributeProgrammaticStreamSerialization;
        attr[0].val.programmaticStreamSerializationAllowed = 1;
        cudaLaunchConfig_t cfg = {};
        cfg.gridDim  = dim3(FA_BLOCKS, 1, 1);
        cfg.blockDim = dim3(256, 1, 1);
        cfg.dynamicSmemBytes = 0;
        cfg.stream = 0;
        cfg.attrs = attr;
        cfg.numAttrs = 1;
        cudaLaunchKernelEx(&cfg, finaleA_kernel, W1);
    }

    // 3) finaleB with PDL: pre-launches during finaleA
    {
        cudaLaunchAttribute attr[1];
        attr[0].id = cudaLaunchAttributeProgrammaticStreamSerialization;
        attr[0].val.programmaticStreamSerializationAllowed = 1;
        cudaLaunchConfig_t cfg = {};
        cfg.gridDim  = dim3(1, 1, 1);
        cfg.blockDim = dim3(256, 1, 1);
        cfg.dynamicSmemBytes = 0;
        cfg.stream = 0;
        cfg.attrs = attr;
        cfg.numAttrs = 1;
        cudaLaunchKernelEx(&cfg, finaleB_kernel, W2, out);
    }
}

// round 12
// speedup vs baseline: 1.0992x; 1.0024x over previous
#include <cuda_runtime.h>
#include <math.h>

static constexpr int NIN   = 8192;
static constexpr int N_HID = 8192;
static constexpr int N_OUT = 1024;
static constexpr int SB    = 32;                          // x-stats blocks (tail)
static constexpr int ROW_BLOCKS   = N_HID + N_OUT;        // 9216
static constexpr int TOTAL_BLOCKS = ROW_BLOCKS + SB;      // 9248
static constexpr int FA_BLOCKS    = 32;

// ---------------- scratch (no allocations allowed) ----------------
__device__ float g_z[NIN];
__device__ float g_hidden[N_HID];
__device__ float g_w1sum[N_HID];
__device__ float g_w2sum[N_OUT];

// x-stats partials (written by big_kernel tail blocks)
__device__ float              g_psum[SB];
__device__ unsigned int       g_pmin[SB];
__device__ unsigned long long g_pmax[SB];
// hidden-stats partials (written by finaleA blocks)
__device__ float              g_qsum[FA_BLOCKS];
__device__ unsigned int       g_qmin[FA_BLOCKS];
__device__ unsigned long long g_qmax[FA_BLOCKS];

__device__ __forceinline__ unsigned int fkey(float v) {
    unsigned u = __float_as_uint(v);
    return (u & 0x80000000u) ? ~u : (u | 0x80000000u);
}
__device__ __forceinline__ float fdec(unsigned int k) {
    unsigned u = (k & 0x80000000u) ? (k ^ 0x80000000u) : ~k;
    return __uint_as_float(u);
}

// PDL device-side primitives (sm_90+)
__device__ __forceinline__ void pdl_trigger() {
    asm volatile("griddepcontrol.launch_dependents;" ::: "memory");
}
__device__ __forceinline__ void pdl_wait() {
    asm volatile("griddepcontrol.wait;" ::: "memory");
}

// ---------------------------------------------------------------------------
// big_kernel — IDENTICAL R8 stream; PDL trigger only AFTER each block's loads,
// so the dependent grid launches during the last wave's reduce phase and never
// competes with the stream.
//   bids [0, 9216)   : W row sums (pure stream)
//   bids [9216, 9248): z = exp(x) + x-stats partials (free tail wave)
// ---------------------------------------------------------------------------
__global__ void __launch_bounds__(256) big_kernel(const float* __restrict__ x,
                                                  const float* __restrict__ W1,
                                                  const float* __restrict__ W2)
{
    const int bid = blockIdx.x;
    const int tid = threadIdx.x;

    if (bid >= ROW_BLOCKS) {
        const int sb = bid - ROW_BLOCKS;
        const int j  = sb * 256 + tid;
        const float v = expf(x[j]);
        g_z[j] = v;
        pdl_trigger();                       // work issued; allow dependents

        __shared__ float              ss[256];
        __shared__ unsigned int       smn[256];
        __shared__ unsigned long long smx[256];
        ss[tid]  = v;
        const unsigned k = fkey(v);
        smn[tid] = k;
        smx[tid] = ((unsigned long long)k << 32) | (unsigned)j;
        __syncthreads();
        for (int o = 128; o > 0; o >>= 1) {
            if (tid < o) {
                ss[tid]  += ss[tid + o];
                smn[tid]  = min(smn[tid], smn[tid + o]);
                smx[tid]  = max(smx[tid], smx[tid + o]);
            }
            __syncthreads();
        }
        if (tid == 0) {
            g_psum[sb] = ss[0];
            g_pmin[sb] = smn[0];
            g_pmax[sb] = smx[0];
        }
        return;
    }

    const bool isW2 = (bid >= N_HID);
    const float* __restrict__ W = isW2 ? W2 : W1;
    const int  row  = isW2 ? (bid - N_HID) : bid;
    const float4* __restrict__ Wr =
        reinterpret_cast<const float4*>(W + (size_t)row * NIN);

    float acc = 0.f;
    #pragma unroll
    for (int i = 0; i < NIN / 4 / 256; ++i) {
        float4 v = __ldcs(Wr + tid + i * 256);
        acc += (v.x + v.y) + (v.z + v.w);
    }
    pdl_trigger();                           // loads issued; allow dependents

    #pragma unroll
    for (int o = 16; o > 0; o >>= 1) acc += __shfl_down_sync(0xffffffffu, acc, o);

    __shared__ float swp[8];
    const int wid = tid >> 5, lane = tid & 31;
    if (lane == 0) swp[wid] = acc;
    __syncthreads();

    if (tid == 0) {
        float Wsum = 0.f;
        #pragma unroll
        for (int w = 0; w < 8; ++w) Wsum += swp[w];
        if (isW2) g_w2sum[row] = Wsum; else g_w1sum[row] = Wsum;
    }
}

// ---------------------------------------------------------------------------
// finaleA (grid 32 x 256) — IDENTICAL to R8 + PDL wait/trigger:
//   1) warp 0 combines the 32 x-stats partials (shuffle tree, fixed order)
//   2) each thread: layer-1 closed form for one row -> g_hidden
//   3) block-reduce the 256 fresh results -> hidden-stats partial
// ---------------------------------------------------------------------------
__global__ void __launch_bounds__(256) finaleA_kernel(const float* __restrict__ W1)
{
    pdl_trigger();   // let finaleB pre-launch (1 block; negligible competition)
    pdl_wait();      // big_kernel's writes fully visible after this

    const int tid = threadIdx.x;
    __shared__ float s_Zsum, s_zmin, s_zmax;
    __shared__ int   s_jlast;

    if (tid < 32) {
        float sum = g_psum[tid];
        unsigned mnk = g_pmin[tid];
        unsigned long long mx = g_pmax[tid];
        #pragma unroll
        for (int o = 16; o > 0; o >>= 1) {
            sum += __shfl_down_sync(0xffffffffu, sum, o);
            mnk  = min(mnk, __shfl_down_sync(0xffffffffu, mnk, o));
            mx   = max(mx,  __shfl_down_sync(0xffffffffu, mx,  o));
        }
        if (tid == 0) {
            s_Zsum  = sum;
            s_zmin  = fdec(mnk);
            s_zmax  = fdec((unsigned)(mx >> 32));
            s_jlast = (int)(unsigned)mx;
        }
    }
    __syncthreads();

    const float Zsum = s_Zsum, zmin = s_zmin, zmax = s_zmax;
    const int   jlast = s_jlast;
    const int   r = blockIdx.x * 256 + tid;
    const float Wsum = g_w1sum[r];
    const float tmp = Wsum * Zsum / (Wsum - 1.f);
    float result = INFINITY;

    if (Wsum > 1.f) {
        if (zmin <= tmp) {                        // first mismatch at i=0 -> k=n-1
            float Wc = Wsum - W1[(size_t)r * NIN + jlast];
            float Zc = Zsum - zmax;
            result = Wc * Zc / (Wc - 1.f);
        }                                         // else: no mismatch -> inf
    } else {
        // rare general path (never taken for this data): serial row scan
        int cnt = 0; float sle = 0.f, wle = 0.f, m = -INFINITY; int jm = -1;
        for (int j = 0; j < NIN; ++j) {
            float zj = g_z[j];
            if (zj <= tmp) {
                cnt++; sle += zj; wle += W1[(size_t)r * NIN + j];
                if (zj > m || (zj == m && j > jm)) { m = zj; jm = j; }
            }
        }
        if (cnt == NIN) {
        } else if (cnt == 0) {
            float Wc = Wsum - W1[(size_t)r * NIN + jlast];
            float Zc = Zsum - zmax;
            result = Wc * Zc / (Wc - 1.f);
        } else if (cnt - 1 != 0) {
            float Zc = sle - m;
            float Wc = wle - W1[(size_t)r * NIN + jm];
            result = Wc * Zc / (Wc - 1.f);
        }
    }
    g_hidden[r] = result;

    // ---- reduce this block's 256 results to a hidden-stats partial ----
    __shared__ float              hs[256];
    __shared__ unsigned int       hn[256];
    __shared__ unsigned long long hx[256];
    hs[tid] = result;
    const unsigned hk = fkey(result);
    hn[tid] = hk;
    hx[tid] = ((unsigned long long)hk << 32) | (unsigned)r;
    __syncthreads();
    for (int o = 128; o > 0; o >>= 1) {
        if (tid < o) {
            hs[tid] += hs[tid + o];
            hn[tid]  = min(hn[tid], hn[tid + o]);
            hx[tid]  = max(hx[tid], hx[tid + o]);
        }
        __syncthreads();
    }
    if (tid == 0) {
        g_qsum[blockIdx.x] = hs[0];
        g_qmin[blockIdx.x] = hn[0];
        g_qmax[blockIdx.x] = hx[0];
    }
}

// ---------------------------------------------------------------------------
// finaleB (1 block x 256) — IDENTICAL to R8 + PDL wait: combine 32 hidden
// partials (one warp, fixed order), then layer-2 closed form (4 rows/thread).
// ---------------------------------------------------------------------------
__global__ void __launch_bounds__(256) finaleB_kernel(const float* __restrict__ W2,
                                                      float* __restrict__ out)
{
    pdl_wait();      // finaleA's writes fully visible after this

    const int tid = threadIdx.x;
    __shared__ float s_Zsum, s_zmin, s_zmax;
    __shared__ int   s_jlast;

    if (tid < 32) {
        float sum = g_qsum[tid];
        unsigned mnk = g_qmin[tid];
        unsigned long long mx = g_qmax[tid];
        #pragma unroll
        for (int o = 16; o > 0; o >>= 1) {
            sum += __shfl_down_sync(0xffffffffu, sum, o);
            mnk  = min(mnk, __shfl_down_sync(0xffffffffu, mnk, o));
            mx   = max(mx,  __shfl_down_sync(0xffffffffu, mx,  o));
        }
        if (tid == 0) {
            s_Zsum  = sum;
            s_zmin  = fdec(mnk);
            s_zmax  = fdec((unsigned)(mx >> 32));
            s_jlast = (int)(unsigned)mx;
        }
    }
    __syncthreads();

    const float Zsum = s_Zsum, zmin = s_zmin, zmax = s_zmax;
    const int   jlast = s_jlast;

    #pragma unroll
    for (int r = tid; r < N_OUT; r += 256) {
        const float Wsum = g_w2sum[r];
        const float tmp = Wsum * Zsum / (Wsum - 1.f);
        float result = INFINITY;

        if (Wsum > 1.f) {
            if (zmin <= tmp) {
                float Wc = Wsum - W2[(size_t)r * NIN + jlast];
                float Zc = Zsum - zmax;
                result = Wc * Zc / (Wc - 1.f);
            }
        } else {
            // rare general path (never taken for this data): serial row scan
            int cnt = 0; float sle = 0.f, wle = 0.f, m = -INFINITY; int jmm = -1;
            for (int j = 0; j < NIN; ++j) {
                float zj = g_hidden[j];
                if (zj <= tmp) {
                    cnt++; sle += zj; wle += W2[(size_t)r * NIN + j];
                    if (zj > m || (zj == m && j > jmm)) { m = zj; jmm = j; }
                }
            }
            if (cnt == NIN) {
            } else if (cnt == 0) {
                float Wc = Wsum - W2[(size_t)r * NIN + jlast];
                float Zc = Zsum - zmax;
                result = Wc * Zc / (Wc - 1.f);
            } else if (cnt - 1 != 0) {
                float Zc = sle - m;
                float Wc = wle - W2[(size_t)r * NIN + jmm];
                result = Wc * Zc / (Wc - 1.f);
            }
        }
        out[r] = result;
    }
}

extern "C" void kernel_launch(void* const* d_in, const int* in_sizes, int n_in,
                              void* d_out, int out_size)
{
    const float* x  = (const float*)d_in[0];
    const float* W1 = (const float*)d_in[1];
    const float* W2 = (const float*)d_in[2];
    float* out = (float*)d_out;

    // 1) stream + tail stats (plain launch)
    big_kernel<<<TOTAL_BLOCKS, 256>>>(x, W1, W2);

    // 2) finaleA with PDL (launches during big_kernel's last-wave reduce phase)
    {
        cudaLaunchAttribute attr[1];
        attr[0].id = cudaLaunchAttributeProgrammaticStreamSerialization;
        attr[0].val.programmaticStreamSerializationAllowed = 1;
        cudaLaunchConfig_t cfg = {};
        cfg.gridDim  = dim3(FA_BLOCKS, 1, 1);
        cfg.blockDim = dim3(256, 1, 1);
        cfg.dynamicSmemBytes = 0;
        cfg.stream = 0;
        cfg.attrs = attr;
        cfg.numAttrs = 1;
        cudaLaunchKernelEx(&cfg, finaleA_kernel, W1);
    }

    // 3) finaleB with PDL (pre-launches during finaleA)
    {
        cudaLaunchAttribute attr[1];
        attr[0].id = cudaLaunchAttributeProgrammaticStreamSerialization;
        attr[0].val.programmaticStreamSerializationAllowed = 1;
        cudaLaunchConfig_t cfg = {};
        cfg.gridDim  = dim3(1, 1, 1);
        cfg.blockDim = dim3(256, 1, 1);
        cfg.dynamicSmemBytes = 0;
        cfg.stream = 0;
        cfg.attrs = attr;
        cfg.numAttrs = 1;
        cudaLaunchKernelEx(&cfg, finaleB_kernel, W2, out);
    }
}

// round 13
// speedup vs baseline: 1.1398x; 1.0369x over previous
#include <cuda_runtime.h>
#include <math.h>

static constexpr int NIN   = 8192;
static constexpr int N_HID = 8192;
static constexpr int N_OUT = 1024;
static constexpr int SB    = 32;                      // statsx blocks
static constexpr int ROW_BLOCKS = N_HID + N_OUT;      // 9216

// ---------------- scratch (no allocations allowed) ----------------
__device__ float g_z[NIN];
__device__ float g_hidden[N_HID];
__device__ float g_w2sum[N_OUT];

// x-stats partials (written by statsx_kernel)
__device__ float              g_psum[SB];
__device__ unsigned int       g_pmin[SB];
__device__ unsigned long long g_pmax[SB];

__device__ __forceinline__ unsigned int fkey(float v) {
    unsigned u = __float_as_uint(v);
    return (u & 0x80000000u) ? ~u : (u | 0x80000000u);
}
__device__ __forceinline__ float fdec(unsigned int k) {
    unsigned u = (k & 0x80000000u) ? (k ^ 0x80000000u) : ~k;
    return __uint_as_float(u);
}

// PDL device-side primitives (sm_90+)
__device__ __forceinline__ void pdl_trigger() {
    asm volatile("griddepcontrol.launch_dependents;" ::: "memory");
}
__device__ __forceinline__ void pdl_wait() {
    asm volatile("griddepcontrol.wait;" ::: "memory");
}

// ---------------------------------------------------------------------------
// statsx (grid 32 x 256): z = exp(x) + per-block stats partials.
// Triggers at entry so big_kernel pre-launches immediately and overlaps.
// ---------------------------------------------------------------------------
__global__ void __launch_bounds__(256) statsx_kernel(const float* __restrict__ x)
{
    pdl_trigger();                        // let big_kernel start right away

    const int tid = threadIdx.x;
    const int j   = blockIdx.x * 256 + tid;
    const float v = expf(x[j]);
    g_z[j] = v;

    __shared__ float              ss[256];
    __shared__ unsigned int       smn[256];
    __shared__ unsigned long long smx[256];
    ss[tid]  = v;
    const unsigned k = fkey(v);
    smn[tid] = k;
    smx[tid] = ((unsigned long long)k << 32) | (unsigned)j;
    __syncthreads();
    for (int o = 128; o > 0; o >>= 1) {
        if (tid < o) {
            ss[tid]  += ss[tid + o];
            smn[tid]  = min(smn[tid], smn[tid + o]);
            smx[tid]  = max(smx[tid], smx[tid + o]);
        }
        __syncthreads();
    }
    if (tid == 0) {
        g_psum[blockIdx.x] = ss[0];
        g_pmin[blockIdx.x] = smn[0];
        g_pmax[blockIdx.x] = smx[0];
    }
}

// ---------------------------------------------------------------------------
// big_kernel (grid 9216): the proven streaming loop + inline layer-1 closed
// form in each row block's tail (R2/R4/R5-proven, zero stream cost).
//   bids [0, 8192)     : W1 row sum -> closed form -> g_hidden
//   bids [8192, 9216)  : W2 row sum -> g_w2sum
// pdl_wait sits AFTER the loads: statsx is long done by then (no stall).
// Late pdl_trigger lets the finale pre-launch during the last wave.
// ---------------------------------------------------------------------------
__global__ void __launch_bounds__(256) big_kernel(const float* __restrict__ W1,
                                                  const float* __restrict__ W2)
{
    const int bid = blockIdx.x;
    const int tid = threadIdx.x;
    const bool isW2 = (bid >= N_HID);
    const float* __restrict__ W = isW2 ? W2 : W1;
    const int  row  = isW2 ? (bid - N_HID) : bid;
    const float4* __restrict__ Wr =
        reinterpret_cast<const float4*>(W + (size_t)row * NIN);

    float acc = 0.f;
    #pragma unroll
    for (int i = 0; i < NIN / 4 / 256; ++i) {
        float4 v = __ldcs(Wr + tid + i * 256);
        acc += (v.x + v.y) + (v.z + v.w);
    }
    pdl_trigger();                        // loads issued; allow finale launch

    #pragma unroll
    for (int o = 16; o > 0; o >>= 1) acc += __shfl_down_sync(0xffffffffu, acc, o);

    __shared__ float swp[8];
    const int wid = tid >> 5, lane = tid & 31;
    if (lane == 0) swp[wid] = acc;
    __syncthreads();

    if (isW2) {
        if (tid == 0) {
            float Wsum = 0.f;
            #pragma unroll
            for (int w = 0; w < 8; ++w) Wsum += swp[w];
            g_w2sum[row] = Wsum;
        }
        return;
    }

    // ---- inline layer-1 closed form (warp 0 only) ----
    if (wid == 0) {
        pdl_wait();                       // statsx writes visible (done long ago)

        // combine the 32 x-stats partials: one lane per partial, shuffle tree
        float sum = g_psum[lane];
        unsigned mnk = g_pmin[lane];
        unsigned long long mx = g_pmax[lane];
        #pragma unroll
        for (int o = 16; o > 0; o >>= 1) {
            sum += __shfl_down_sync(0xffffffffu, sum, o);
            mnk  = min(mnk, __shfl_down_sync(0xffffffffu, mnk, o));
            mx   = max(mx,  __shfl_down_sync(0xffffffffu, mx,  o));
        }

        if (lane == 0) {
            const float Zsum = sum;
            const float zmin = fdec(mnk);
            const float zmax = fdec((unsigned)(mx >> 32));
            const int   jlast = (int)(unsigned)mx;

            float Wsum = 0.f;
            #pragma unroll
            for (int w = 0; w < 8; ++w) Wsum += swp[w];

            const float tmp = Wsum * Zsum / (Wsum - 1.f);
            float result = INFINITY;
            if (Wsum > 1.f) {
                if (zmin <= tmp) {                 // first mismatch at i=0 -> k=n-1
                    float Wc = Wsum - W[(size_t)row * NIN + jlast];
                    float Zc = Zsum - zmax;
                    result = Wc * Zc / (Wc - 1.f);
                }                                  // else: no mismatch -> inf
            } else {
                // rare general path (never taken for this data): serial row scan
                int cnt = 0; float sle = 0.f, wle = 0.f, m = -INFINITY; int jm = -1;
                for (int j = 0; j < NIN; ++j) {
                    float zj = g_z[j];
                    if (zj <= tmp) {
                        cnt++; sle += zj; wle += W[(size_t)row * NIN + j];
                        if (zj > m || (zj == m && j > jm)) { m = zj; jm = j; }
                    }
                }
                if (cnt == NIN) {
                } else if (cnt == 0) {
                    float Wc = Wsum - W[(size_t)row * NIN + jlast];
                    float Zc = Zsum - zmax;
                    result = Wc * Zc / (Wc - 1.f);
                } else if (cnt - 1 != 0) {
                    float Zc = sle - m;
                    float Wc = wle - W[(size_t)row * NIN + jm];
                    result = Wc * Zc / (Wc - 1.f);
                }
            }
            g_hidden[row] = result;
        }
    }
}

// ---------------------------------------------------------------------------
// finale (1 block x 1024), PDL-waited on big_kernel:
//   phase 1: hidden stats over g_hidden (32 KB coalesced, L2-hot; fixed tree)
//   phase 2: layer-2 closed form, one output row per thread -> out
// ---------------------------------------------------------------------------
__global__ void __launch_bounds__(1024) finale_kernel(const float* __restrict__ W2,
                                                      float* __restrict__ out)
{
    pdl_wait();                           // all of big_kernel's writes visible

    const int tid = threadIdx.x;

    float sum = 0.f, mn = INFINITY, mx = -INFINITY;
    int jm = -1;
    #pragma unroll
    for (int i = 0; i < N_HID / 1024; ++i) {
        const int j = tid + i * 1024;
        float v = g_hidden[j];
        sum += v;
        mn = fminf(mn, v);
        if (v > mx || (v == mx && j > jm)) { mx = v; jm = j; }
    }
    __shared__ float ss[1024], smn[1024], smx[1024];
    __shared__ int   sj[1024];
    ss[tid] = sum; smn[tid] = mn; smx[tid] = mx; sj[tid] = jm;
    __syncthreads();
    for (int o = 512; o > 0; o >>= 1) {
        if (tid < o) {
            ss[tid]  += ss[tid + o];
            smn[tid]  = fminf(smn[tid], smn[tid + o]);
            float v2 = smx[tid + o]; int i2 = sj[tid + o];
            if (v2 > smx[tid] || (v2 == smx[tid] && i2 > sj[tid])) { smx[tid] = v2; sj[tid] = i2; }
        }
        __syncthreads();
    }
    const float Zsum = ss[0];
    const float zmin = smn[0];
    const float zmax = smx[0];
    const int   jlast = sj[0];
    __syncthreads();

    const int r = tid;
    if (r >= N_OUT) return;

    const float Wsum = g_w2sum[r];
    const float tmp = Wsum * Zsum / (Wsum - 1.f);
    float result = INFINITY;

    if (Wsum > 1.f) {
        if (zmin <= tmp) {
            float Wc = Wsum - W2[(size_t)r * NIN + jlast];
            float Zc = Zsum - zmax;
            result = Wc * Zc / (Wc - 1.f);
        }
    } else {
        // rare general path (never taken for this data): serial row scan
        int cnt = 0; float sle = 0.f, wle = 0.f, m = -INFINITY; int jmm = -1;
        for (int j = 0; j < NIN; ++j) {
            float zj = g_hidden[j];
            if (zj <= tmp) {
                cnt++; sle += zj; wle += W2[(size_t)r * NIN + j];
                if (zj > m || (zj == m && j > jmm)) { m = zj; jmm = j; }
            }
        }
        if (cnt == NIN) {
        } else if (cnt == 0) {
            float Wc = Wsum - W2[(size_t)r * NIN + jlast];
            float Zc = Zsum - zmax;
            result = Wc * Zc / (Wc - 1.f);
        } else if (cnt - 1 != 0) {
            float Zc = sle - m;
            float Wc = wle - W2[(size_t)r * NIN + jmm];
            result = Wc * Zc / (Wc - 1.f);
        }
    }
    out[r] = result;
}

extern "C" void kernel_launch(void* const* d_in, const int* in_sizes, int n_in,
                              void* d_out, int out_size)
{
    const float* x  = (const float*)d_in[0];
    const float* W1 = (const float*)d_in[1];
    const float* W2 = (const float*)d_in[2];
    float* out = (float*)d_out;

    // 1) statsx (plain): triggers at entry so big_kernel overlaps it entirely
    statsx_kernel<<<SB, 256>>>(x);

    // 2) big_kernel with PDL: pre-launches during statsx; waits (no-op) after loads
    {
        cudaLaunchAttribute attr[1];
        attr[0].id = cudaLaunchAttributeProgrammaticStreamSerialization;
        attr[0].val.programmaticStreamSerializationAllowed = 1;
        cudaLaunchConfig_t cfg = {};
        cfg.gridDim  = dim3(ROW_BLOCKS, 1, 1);
        cfg.blockDim = dim3(256, 1, 1);
        cfg.dynamicSmemBytes = 0;
        cfg.stream = 0;
        cfg.attrs = attr;
        cfg.numAttrs = 1;
        cudaLaunchKernelEx(&cfg, big_kernel, W1, W2);
    }

    // 3) finale with PDL: pre-launches during big_kernel's last wave
    {
        cudaLaunchAttribute attr[1];
        attr[0].id = cudaLaunchAttributeProgrammaticStreamSerialization;
        attr[0].val.programmaticStreamSerializationAllowed = 1;
        cudaLaunchConfig_t cfg = {};
        cfg.gridDim  = dim3(1, 1, 1);
        cfg.blockDim = dim3(1024, 1, 1);
        cfg.dynamicSmemBytes = 0;
        cfg.stream = 0;
        cfg.attrs = attr;
        cfg.numAttrs = 1;
        cudaLaunchKernelEx(&cfg, finale_kernel, W2, out);
    }
}

// round 14
// speedup vs baseline: 1.1554x; 1.0137x over previous
#include <cuda_runtime.h>
#include <math.h>

static constexpr int NIN   = 8192;
static constexpr int N_HID = 8192;
static constexpr int N_OUT = 1024;
static constexpr int SB    = 32;                          // stats blocks (grid FRONT)
static constexpr int ROW_BLOCKS   = N_HID + N_OUT;        // 9216
static constexpr int TOTAL_BLOCKS = SB + ROW_BLOCKS;      // 9248

// ---------------- scratch (no allocations allowed) ----------------
__device__ float g_z[NIN];
__device__ float g_hidden[N_HID];
__device__ float g_w2sum[N_OUT];

// x-stats partials (written by the 32 front blocks of big_kernel)
__device__ float              g_psum[SB];
__device__ unsigned int       g_pmin[SB];
__device__ unsigned long long g_pmax[SB];
__device__ unsigned int       g_done = 0;   // #stats blocks published (reset by finale)

__device__ __forceinline__ unsigned int fkey(float v) {
    unsigned u = __float_as_uint(v);
    return (u & 0x80000000u) ? ~u : (u | 0x80000000u);
}
__device__ __forceinline__ float fdec(unsigned int k) {
    unsigned u = (k & 0x80000000u) ? (k ^ 0x80000000u) : ~k;
    return __uint_as_float(u);
}

// PDL device-side primitives (sm_90+)
__device__ __forceinline__ void pdl_trigger() {
    asm volatile("griddepcontrol.launch_dependents;" ::: "memory");
}
__device__ __forceinline__ void pdl_wait() {
    asm volatile("griddepcontrol.wait;" ::: "memory");
}

// ---------------------------------------------------------------------------
// big_kernel (grid 9248):
//   bids [0, 32)     : z = exp(x) + x-stats partials, publish via g_done
//                      (wave-1 resident; done ~3us in)
//   bids [32, 9248)  : the proven streaming row loop; W1 blocks' warp0 tail
//                      spins (expected 0 iters) on g_done, then does the
//                      inline layer-1 closed form -> g_hidden.
// Late pdl_trigger lets the finale pre-launch during the last wave.
// ---------------------------------------------------------------------------
__global__ void __launch_bounds__(256) big_kernel(const float* __restrict__ x,
                                                  const float* __restrict__ W1,
                                                  const float* __restrict__ W2)
{
    const int bid = blockIdx.x;
    const int tid = threadIdx.x;

    if (bid < SB) {
        // -------- stats block: one element per thread --------
        const int j = bid * 256 + tid;
        const float v = expf(x[j]);
        g_z[j] = v;

        __shared__ float              ss[256];
        __shared__ unsigned int       smn[256];
        __shared__ unsigned long long smx[256];
        ss[tid]  = v;
        const unsigned k = fkey(v);
        smn[tid] = k;
        smx[tid] = ((unsigned long long)k << 32) | (unsigned)j;
        __syncthreads();
        for (int o = 128; o > 0; o >>= 1) {
            if (tid < o) {
                ss[tid]  += ss[tid + o];
                smn[tid]  = min(smn[tid], smn[tid + o]);
                smx[tid]  = max(smx[tid], smx[tid + o]);
            }
            __syncthreads();
        }
        if (tid == 0) {
            g_psum[bid] = ss[0];
            g_pmin[bid] = smn[0];
            g_pmax[bid] = smx[0];
            __threadfence();                       // partials visible before count
            atomicAdd(&g_done, 1u);
        }
        pdl_trigger();
        return;
    }

    // -------- row block (proven streaming loop; untouched) --------
    const int  rb   = bid - SB;
    const bool isW2 = (rb >= N_HID);
    const float* __restrict__ W = isW2 ? W2 : W1;
    const int  row  = isW2 ? (rb - N_HID) : rb;
    const float4* __restrict__ Wr =
        reinterpret_cast<const float4*>(W + (size_t)row * NIN);

    float acc = 0.f;
    #pragma unroll
    for (int i = 0; i < NIN / 4 / 256; ++i) {
        float4 v = __ldcs(Wr + tid + i * 256);
        acc += (v.x + v.y) + (v.z + v.w);
    }
    pdl_trigger();                                 // loads issued; allow finale

    #pragma unroll
    for (int o = 16; o > 0; o >>= 1) acc += __shfl_down_sync(0xffffffffu, acc, o);

    __shared__ float swp[8];
    const int wid = tid >> 5, lane = tid & 31;
    if (lane == 0) swp[wid] = acc;
    __syncthreads();

    if (isW2) {
        if (tid == 0) {
            float Wsum = 0.f;
            #pragma unroll
            for (int w = 0; w < 8; ++w) Wsum += swp[w];
            g_w2sum[row] = Wsum;
        }
        return;
    }

    // ---- inline layer-1 closed form (warp 0 only) ----
    if (wid == 0) {
        // stats blocks are wave-1 and finish ~3us in; W1 tails arrive >=6us in,
        // so this spin is expected to take ZERO iterations.
        while (*(volatile unsigned int*)&g_done < SB) { __nanosleep(64); }
        asm volatile("" ::: "memory");             // don't hoist loads above spin

        // combine the 32 x-stats partials: one lane per partial, shuffle tree
        float sum = g_psum[lane];
        unsigned mnk = g_pmin[lane];
        unsigned long long mx = g_pmax[lane];
        #pragma unroll
        for (int o = 16; o > 0; o >>= 1) {
            sum += __shfl_down_sync(0xffffffffu, sum, o);
            mnk  = min(mnk, __shfl_down_sync(0xffffffffu, mnk, o));
            mx   = max(mx,  __shfl_down_sync(0xffffffffu, mx,  o));
        }

        if (lane == 0) {
            const float Zsum = sum;
            const float zmin = fdec(mnk);
            const float zmax = fdec((unsigned)(mx >> 32));
            const int   jlast = (int)(unsigned)mx;

            float Wsum = 0.f;
            #pragma unroll
            for (int w = 0; w < 8; ++w) Wsum += swp[w];

            const float tmp = Wsum * Zsum / (Wsum - 1.f);
            float result = INFINITY;
            if (Wsum > 1.f) {
                if (zmin <= tmp) {                 // first mismatch at i=0 -> k=n-1
                    float Wc = Wsum - W[(size_t)row * NIN + jlast];
                    float Zc = Zsum - zmax;
                    result = Wc * Zc / (Wc - 1.f);
                }                                  // else: no mismatch -> inf
            } else {
                // rare general path (never taken for this data): serial row scan
                int cnt = 0; float sle = 0.f, wle = 0.f, m = -INFINITY; int jm = -1;
                for (int j = 0; j < NIN; ++j) {
                    float zj = g_z[j];
                    if (zj <= tmp) {
                        cnt++; sle += zj; wle += W[(size_t)row * NIN + j];
                        if (zj > m || (zj == m && j > jm)) { m = zj; jm = j; }
                    }
                }
                if (cnt == NIN) {
                } else if (cnt == 0) {
                    float Wc = Wsum - W[(size_t)row * NIN + jlast];
                    float Zc = Zsum - zmax;
                    result = Wc * Zc / (Wc - 1.f);
                } else if (cnt - 1 != 0) {
                    float Zc = sle - m;
                    float Wc = wle - W[(size_t)row * NIN + jm];
                    result = Wc * Zc / (Wc - 1.f);
                }
            }
            g_hidden[row] = result;
        }
    }
}

// ---------------------------------------------------------------------------
// finale (1 block x 1024), PDL-waited on big_kernel:
//   phase 1: hidden stats over g_hidden (32 KB coalesced, L2-hot; fixed tree)
//   phase 2: layer-2 closed form, one output row per thread -> out
//   also resets g_done for the next graph replay.
// ---------------------------------------------------------------------------
__global__ void __launch_bounds__(1024) finale_kernel(const float* __restrict__ W2,
                                                      float* __restrict__ out)
{
    pdl_wait();                           // all of big_kernel's writes visible

    const int tid = threadIdx.x;
    if (tid == 0) g_done = 0;             // reset for next replay

    float sum = 0.f, mn = INFINITY, mx = -INFINITY;
    int jm = -1;
    #pragma unroll
    for (int i = 0; i < N_HID / 1024; ++i) {
        const int j = tid + i * 1024;
        float v = g_hidden[j];
        sum += v;
        mn = fminf(mn, v);
        if (v > mx || (v == mx && j > jm)) { mx = v; jm = j; }
    }
    __shared__ float ss[1024], smn[1024], smx[1024];
    __shared__ int   sj[1024];
    ss[tid] = sum; smn[tid] = mn; smx[tid] = mx; sj[tid] = jm;
    __syncthreads();
    for (int o = 512; o > 0; o >>= 1) {
        if (tid < o) {
            ss[tid]  += ss[tid + o];
            smn[tid]  = fminf(smn[tid], smn[tid + o]);
            float v2 = smx[tid + o]; int i2 = sj[tid + o];
            if (v2 > smx[tid] || (v2 == smx[tid] && i2 > sj[tid])) { smx[tid] = v2; sj[tid] = i2; }
        }
        __syncthreads();
    }
    const float Zsum = ss[0];
    const float zmin = smn[0];
    const float zmax = smx[0];
    const int   jlast = sj[0];
    __syncthreads();

    const int r = tid;
    if (r >= N_OUT) return;

    const float Wsum = g_w2sum[r];
    const float tmp = Wsum * Zsum / (Wsum - 1.f);
    float result = INFINITY;

    if (Wsum > 1.f) {
        if (zmin <= tmp) {
            float Wc = Wsum - W2[(size_t)r * NIN + jlast];
            float Zc = Zsum - zmax;
            result = Wc * Zc / (Wc - 1.f);
        }
    } else {
        // rare general path (never taken for this data): serial row scan
        int cnt = 0; float sle = 0.f, wle = 0.f, m = -INFINITY; int jmm = -1;
        for (int j = 0; j < NIN; ++j) {
            float zj = g_hidden[j];
            if (zj <= tmp) {
                cnt++; sle += zj; wle += W2[(size_t)r * NIN + j];
                if (zj > m || (zj == m && j > jmm)) { m = zj; jmm = j; }
            }
        }
        if (cnt == NIN) {
        } else if (cnt == 0) {
            float Wc = Wsum - W2[(size_t)r * NIN + jlast];
            float Zc = Zsum - zmax;
            result = Wc * Zc / (Wc - 1.f);
        } else if (cnt - 1 != 0) {
            float Zc = sle - m;
            float Wc = wle - W2[(size_t)r * NIN + jmm];
            result = Wc * Zc / (Wc - 1.f);
        }
    }
    out[r] = result;
}

extern "C" void kernel_launch(void* const* d_in, const int* in_sizes, int n_in,
                              void* d_out, int out_size)
{
    const float* x  = (const float*)d_in[0];
    const float* W1 = (const float*)d_in[1];
    const float* W2 = (const float*)d_in[2];
    float* out = (float*)d_out;

    // 1) stream + front stats (plain launch)
    big_kernel<<<TOTAL_BLOCKS, 256>>>(x, W1, W2);

    // 2) finale with PDL: pre-launches during big_kernel's last wave
    {
        cudaLaunchAttribute attr[1];
        attr[0].id = cudaLaunchAttributeProgrammaticStreamSerialization;
        attr[0].val.programmaticStreamSerializationAllowed = 1;
        cudaLaunchConfig_t cfg = {};
        cfg.gridDim  = dim3(1, 1, 1);
        cfg.blockDim = dim3(1024, 1, 1);
        cfg.dynamicSmemBytes = 0;
        cfg.stream = 0;
        cfg.attrs = attr;
        cfg.numAttrs = 1;
        cudaLaunchKernelEx(&cfg, finale_kernel, W2, out);
    }
}

// round 15
// speedup vs baseline: 1.1873x; 1.0276x over previous
#include <cuda_runtime.h>
#include <math.h>

static constexpr int NIN   = 8192;
static constexpr int N_HID = 8192;
static constexpr int N_OUT = 1024;
static constexpr int SB    = 32;                          // stats blocks (grid FRONT)
static constexpr int ROW_BLOCKS   = N_HID + N_OUT;        // 9216
static constexpr int TOTAL_BLOCKS = SB + ROW_BLOCKS;      // 9248

#define FP_SCALE 268435456.0   // 2^28 fixed-point for the deterministic hidden sum

// ---------------- scratch (no allocations allowed) ----------------
__device__ float g_z[NIN];
__device__ float g_hidden[N_HID];        // kept for the rare layer-2 path
__device__ float g_w2sum[N_OUT];

// x-stats partials (written by the 32 front blocks of big_kernel)
__device__ float              g_psum[SB];
__device__ unsigned int       g_pmin[SB];
__device__ unsigned long long g_pmax[SB];
__device__ unsigned int       g_done = 0;     // #stats blocks published

// hidden-stats accumulators (deterministic integer atomics; reset by finale)
__device__ long long          gh_sum  = 0;    // fixed-point sum
__device__ unsigned int       gh_minb = 0xFFFFFFFFu;   // min key
__device__ unsigned long long gh_maxp = 0;    // (key<<32)|idx  -> last-argmax
__device__ unsigned int       gh_inf  = 0;    // #inf hidden values

__device__ __forceinline__ unsigned int fkey(float v) {
    unsigned u = __float_as_uint(v);
    return (u & 0x80000000u) ? ~u : (u | 0x80000000u);
}
__device__ __forceinline__ float fdec(unsigned int k) {
    unsigned u = (k & 0x80000000u) ? (k ^ 0x80000000u) : ~k;
    return __uint_as_float(u);
}

// PDL device-side primitives (sm_90+)
__device__ __forceinline__ void pdl_trigger() {
    asm volatile("griddepcontrol.launch_dependents;" ::: "memory");
}
__device__ __forceinline__ void pdl_wait() {
    asm volatile("griddepcontrol.wait;" ::: "memory");
}

// ---------------------------------------------------------------------------
// big_kernel (grid 9248):
//   bids [0, 32)     : z = exp(x) + x-stats partials, publish via g_done
//   bids [32, 9248)  : the proven streaming row loop; W1 blocks' warp0 tail
//                      spins (expected 0 iters) on g_done, does the inline
//                      layer-1 closed form -> g_hidden, and accumulates the
//                      hidden stats via DETERMINISTIC integer atomics.
// ---------------------------------------------------------------------------
__global__ void __launch_bounds__(256) big_kernel(const float* __restrict__ x,
                                                  const float* __restrict__ W1,
                                                  const float* __restrict__ W2)
{
    const int bid = blockIdx.x;
    const int tid = threadIdx.x;

    if (bid < SB) {
        // -------- stats block: one element per thread --------
        const int j = bid * 256 + tid;
        const float v = expf(x[j]);
        g_z[j] = v;

        __shared__ float              ss[256];
        __shared__ unsigned int       smn[256];
        __shared__ unsigned long long smx[256];
        ss[tid]  = v;
        const unsigned k = fkey(v);
        smn[tid] = k;
        smx[tid] = ((unsigned long long)k << 32) | (unsigned)j;
        __syncthreads();
        for (int o = 128; o > 0; o >>= 1) {
            if (tid < o) {
                ss[tid]  += ss[tid + o];
                smn[tid]  = min(smn[tid], smn[tid + o]);
                smx[tid]  = max(smx[tid], smx[tid + o]);
            }
            __syncthreads();
        }
        if (tid == 0) {
            g_psum[bid] = ss[0];
            g_pmin[bid] = smn[0];
            g_pmax[bid] = smx[0];
            __threadfence();                       // partials visible before count
            atomicAdd(&g_done, 1u);
        }
        pdl_trigger();
        return;
    }

    // -------- row block (proven streaming loop; untouched) --------
    const int  rb   = bid - SB;
    const bool isW2 = (rb >= N_HID);
    const float* __restrict__ W = isW2 ? W2 : W1;
    const int  row  = isW2 ? (rb - N_HID) : rb;
    const float4* __restrict__ Wr =
        reinterpret_cast<const float4*>(W + (size_t)row * NIN);

    float acc = 0.f;
    #pragma unroll
    for (int i = 0; i < NIN / 4 / 256; ++i) {
        float4 v = __ldcs(Wr + tid + i * 256);
        acc += (v.x + v.y) + (v.z + v.w);
    }
    pdl_trigger();                                 // loads issued; allow finale

    #pragma unroll
    for (int o = 16; o > 0; o >>= 1) acc += __shfl_down_sync(0xffffffffu, acc, o);

    __shared__ float swp[8];
    const int wid = tid >> 5, lane = tid & 31;
    if (lane == 0) swp[wid] = acc;
    __syncthreads();

    if (isW2) {
        if (tid == 0) {
            float Wsum = 0.f;
            #pragma unroll
            for (int w = 0; w < 8; ++w) Wsum += swp[w];
            g_w2sum[row] = Wsum;
        }
        return;
    }

    // ---- inline layer-1 closed form (warp 0 only) ----
    if (wid == 0) {
        // stats blocks are wave-1 and finish ~3us in; W1 tails arrive >=6us in.
        while (*(volatile unsigned int*)&g_done < SB) { __nanosleep(64); }
        asm volatile("" ::: "memory");

        // combine the 32 x-stats partials: one lane per partial, shuffle tree
        float sum = g_psum[lane];
        unsigned mnk = g_pmin[lane];
        unsigned long long mx = g_pmax[lane];
        #pragma unroll
        for (int o = 16; o > 0; o >>= 1) {
            sum += __shfl_down_sync(0xffffffffu, sum, o);
            mnk  = min(mnk, __shfl_down_sync(0xffffffffu, mnk, o));
            mx   = max(mx,  __shfl_down_sync(0xffffffffu, mx,  o));
        }

        if (lane == 0) {
            const float Zsum = sum;
            const float zmin = fdec(mnk);
            const float zmax = fdec((unsigned)(mx >> 32));
            const int   jlast = (int)(unsigned)mx;

            float Wsum = 0.f;
            #pragma unroll
            for (int w = 0; w < 8; ++w) Wsum += swp[w];

            const float tmp = Wsum * Zsum / (Wsum - 1.f);
            float result = INFINITY;
            if (Wsum > 1.f) {
                if (zmin <= tmp) {                 // first mismatch at i=0 -> k=n-1
                    float Wc = Wsum - W[(size_t)row * NIN + jlast];
                    float Zc = Zsum - zmax;
                    result = Wc * Zc / (Wc - 1.f);
                }                                  // else: no mismatch -> inf
            } else {
                // rare general path (never taken for this data): serial row scan
                int cnt = 0; float sle = 0.f, wle = 0.f, m = -INFINITY; int jm = -1;
                for (int j = 0; j < NIN; ++j) {
                    float zj = g_z[j];
                    if (zj <= tmp) {
                        cnt++; sle += zj; wle += W[(size_t)row * NIN + j];
                        if (zj > m || (zj == m && j > jm)) { m = zj; jm = j; }
                    }
                }
                if (cnt == NIN) {
                } else if (cnt == 0) {
                    float Wc = Wsum - W[(size_t)row * NIN + jlast];
                    float Zc = Zsum - zmax;
                    result = Wc * Zc / (Wc - 1.f);
                } else if (cnt - 1 != 0) {
                    float Zc = sle - m;
                    float Wc = wle - W[(size_t)row * NIN + jm];
                    result = Wc * Zc / (Wc - 1.f);
                }
            }
            g_hidden[row] = result;

            // ---- deterministic hidden-stats accumulation ----
            const unsigned hk = fkey(result);
            atomicMin(&gh_minb, hk);
            atomicMax(&gh_maxp, ((unsigned long long)hk << 32) | (unsigned)row);
            if (isinf(result)) {
                atomicAdd(&gh_inf, 1u);
            } else {
                atomicAdd((unsigned long long*)&gh_sum,
                          (unsigned long long)__double2ll_rn((double)result * FP_SCALE));
            }
        }
    }
}

// ---------------------------------------------------------------------------
// finale (1 block x 1024), PDL-waited on big_kernel:
//   read the 4 hidden-stats scalars, layer-2 closed form (one row/thread),
//   then reset all accumulators for the next graph replay.
// ---------------------------------------------------------------------------
__global__ void __launch_bounds__(1024) finale_kernel(const float* __restrict__ W2,
                                                      float* __restrict__ out)
{
    pdl_wait();                           // all of big_kernel's writes visible

    const int tid = threadIdx.x;

    const long long          hsum = gh_sum;
    const unsigned int       hmin = gh_minb;
    const unsigned long long hmax = gh_maxp;
    const unsigned int       hinf = gh_inf;

    const float Zsum = hinf ? INFINITY : (float)((double)hsum * (1.0 / FP_SCALE));
    const float zmin = fdec(hmin);
    const float zmax = fdec((unsigned)(hmax >> 32));
    const int   jlast = (int)(unsigned)hmax;

    const int r = tid;
    if (r < N_OUT) {
        const float Wsum = g_w2sum[r];
        const float tmp = Wsum * Zsum / (Wsum - 1.f);
        float result = INFINITY;

        if (Wsum > 1.f) {
            if (zmin <= tmp) {
                float Wc = Wsum - W2[(size_t)r * NIN + jlast];
                float Zc = Zsum - zmax;
                result = Wc * Zc / (Wc - 1.f);
            }
        } else {
            // rare general path (never taken for this data): serial row scan
            int cnt = 0; float sle = 0.f, wle = 0.f, m = -INFINITY; int jmm = -1;
            for (int j = 0; j < NIN; ++j) {
                float zj = g_hidden[j];
                if (zj <= tmp) {
                    cnt++; sle += zj; wle += W2[(size_t)r * NIN + j];
                    if (zj > m || (zj == m && j > jmm)) { m = zj; jmm = j; }
                }
            }
            if (cnt == NIN) {
            } else if (cnt == 0) {
                float Wc = Wsum - W2[(size_t)r * NIN + jlast];
                float Zc = Zsum - zmax;
                result = Wc * Zc / (Wc - 1.f);
            } else if (cnt - 1 != 0) {
                float Zc = sle - m;
                float Wc = wle - W2[(size_t)r * NIN + jmm];
                result = Wc * Zc / (Wc - 1.f);
            }
        }
        out[r] = result;
    }

    // ---- reset accumulators for the next graph replay ----
    __syncthreads();                      // everyone has read the scalars
    if (tid == 0) {
        g_done  = 0;
        gh_sum  = 0;
        gh_minb = 0xFFFFFFFFu;
        gh_maxp = 0ULL;
        gh_inf  = 0u;
    }
}

extern "C" void kernel_launch(void* const* d_in, const int* in_sizes, int n_in,
                              void* d_out, int out_size)
{
    const float* x  = (const float*)d_in[0];
    const float* W1 = (const float*)d_in[1];
    const float* W2 = (const float*)d_in[2];
    float* out = (float*)d_out;

    // 1) stream + front stats + in-stream hidden-stats accumulation
    big_kernel<<<TOTAL_BLOCKS, 256>>>(x, W1, W2);

    // 2) finale with PDL: pre-launches during big_kernel's last wave
    {
        cudaLaunchAttribute attr[1];
        attr[0].id = cudaLaunchAttributeProgrammaticStreamSerialization;
        attr[0].val.programmaticStreamSerializationAllowed = 1;
        cudaLaunchConfig_t cfg = {};
        cfg.gridDim  = dim3(1, 1, 1);
        cfg.blockDim = dim3(1024, 1, 1);
        cfg.dynamicSmemBytes = 0;
        cfg.stream = 0;
        cfg.attrs = attr;
        cfg.numAttrs = 1;
        cudaLaunchKernelEx(&cfg, finale_kernel, W2, out);
    }
}